// round 8
// baseline (speedup 1.0000x reference)
#include <cuda_runtime.h>
#include <cuda_fp16.h>

// GATRoutingModel: 2-layer GAT + FC.  N=50000, E=1600000, F=64.
// Round 8: round-7 skeleton + (a) implicit self-loops (no init kernel;
// g_cur re-zeroed by g2_final -> replay-safe), (b) occupancy-balanced GEMM2
// (64 nodes/block, 4n x 2c per thread).

#define NMAX   50000
#define EMAX   1600000
#define STRIDE 128

__device__ __half  g_h1h[NMAX * 64];
__device__ float   g_feat2[NMAX * 64];
__device__ __half  g_h2h[NMAX * 32];
__device__ float2  g_as1[NMAX];
__device__ float2  g_ad1[NMAX];
__device__ float   g_as2[NMAX];
__device__ float   g_ad2[NMAX];
__device__ int     g_cur[NMAX];            // zero at entry; re-zeroed by g2
__device__ int     g_srcs[NMAX * STRIDE];

__device__ __forceinline__ float warpReduceSum(float v) {
#pragma unroll
    for (int o = 16; o > 0; o >>= 1) v += __shfl_xor_sync(0xffffffffu, v, o);
    return v;
}
__device__ __forceinline__ float halfReduceSum(float v) {
#pragma unroll
    for (int o = 8; o > 0; o >>= 1) v += __shfl_xor_sync(0xffffffffu, v, o);
    return v;
}

// ---------------------------------------------------------------------------
// FAT kernel, interleaved roles: bid%3==0 (while gemm ids last) -> GEMM1
// block (64 nodes, 8n x 2c per thread); otherwise CSR slab fill.
// ---------------------------------------------------------------------------
__global__ void __launch_bounds__(256) k_fat(
        const float* __restrict__ x,
        const float* __restrict__ W1,
        const float* __restrict__ a_src,
        const float* __restrict__ a_dst,
        const int* __restrict__ ei,
        int N, int E, int gemmB) {
    int tid = threadIdx.x;
    int bid = blockIdx.x;
    int q = bid / 3;
    bool isGemm = ((bid % 3) == 0) && (q < gemmB);

    if (!isGemm) {
        // -------- CSR fill: 4 edges/thread via int4, slots from 0 --------
        int gcount = (bid % 3 == 0) ? gemmB : ((q + 1 < gemmB) ? q + 1 : gemmB);
        int fb = bid - gcount;
        int i = fb * 256 + tid;
        int n4 = E >> 2;
        const int4* src4 = (const int4*)ei;
        const int4* dst4 = (const int4*)(ei + E);
        if (i < n4) {
            int4 s = src4[i];
            int4 d = dst4[i];
            int p0 = atomicAdd(&g_cur[d.x], 1);
            int p1 = atomicAdd(&g_cur[d.y], 1);
            int p2 = atomicAdd(&g_cur[d.z], 1);
            int p3 = atomicAdd(&g_cur[d.w], 1);
            if (p0 < STRIDE) g_srcs[d.x * STRIDE + p0] = s.x;
            if (p1 < STRIDE) g_srcs[d.y * STRIDE + p1] = s.y;
            if (p2 < STRIDE) g_srcs[d.z * STRIDE + p2] = s.z;
            if (p3 < STRIDE) g_srcs[d.w * STRIDE + p3] = s.w;
        }
        if (fb == 0 && tid == 0) {
            for (int t = n4 * 4; t < E; t++) {
                int d = ei[E + t];
                int p = atomicAdd(&g_cur[d], 1);
                if (p < STRIDE) g_srcs[d * STRIDE + p] = ei[t];
            }
        }
        return;
    }

    // -------- GEMM1: h1 = x @ W1 (Nx64 @ 64x64) + alpha1 logits --------
    __shared__ float  Ws[64 * 64];
    __shared__ float4 xs[64 * 16];
    for (int i = tid; i < 64 * 64; i += 256) Ws[i] = W1[i];
    int node0 = q * 64;
    const float4* x4 = (const float4*)x;
    for (int i = tid; i < 1024; i += 256) {
        int gi = node0 * 16 + i;
        xs[i] = (gi < N * 16) ? x4[gi] : make_float4(0.f, 0.f, 0.f, 0.f);
    }
    __syncthreads();

    int c2 = tid & 31;          // cols c2 (head0) and c2+32 (head1)
    int wp = tid >> 5;          // warp: nodes wp*8 .. wp*8+7
    float acc0[8] = {0,0,0,0,0,0,0,0};
    float acc1[8] = {0,0,0,0,0,0,0,0};

#pragma unroll
    for (int kk = 0; kk < 64; kk += 8) {
        float w0[8], w1[8];
#pragma unroll
        for (int i = 0; i < 8; i++) {
            w0[i] = Ws[(kk + i) * 64 + c2];
            w1[i] = Ws[(kk + i) * 64 + c2 + 32];
        }
#pragma unroll
        for (int n = 0; n < 8; n++) {
            float4 xa = xs[(wp * 8 + n) * 16 + (kk >> 2)];
            float4 xb = xs[(wp * 8 + n) * 16 + (kk >> 2) + 1];
            acc0[n] += xa.x * w0[0] + xa.y * w0[1] + xa.z * w0[2] + xa.w * w0[3]
                     + xb.x * w0[4] + xb.y * w0[5] + xb.z * w0[6] + xb.w * w0[7];
            acc1[n] += xa.x * w1[0] + xa.y * w1[1] + xa.z * w1[2] + xa.w * w1[3]
                     + xb.x * w1[4] + xb.y * w1[5] + xb.z * w1[6] + xb.w * w1[7];
        }
    }

    float as0 = a_src[c2], as1 = a_src[c2 + 32];
    float ad0 = a_dst[c2], ad1 = a_dst[c2 + 32];

#pragma unroll
    for (int n = 0; n < 8; n++) {
        int node = node0 + wp * 8 + n;
        bool ok = node < N;
        if (ok) {
            g_h1h[node * 64 + c2]      = __float2half(acc0[n]);
            g_h1h[node * 64 + c2 + 32] = __float2half(acc1[n]);
        }
        float s0 = warpReduceSum(acc0[n] * as0);
        float s1 = warpReduceSum(acc1[n] * as1);
        float d0 = warpReduceSum(acc0[n] * ad0);
        float d1 = warpReduceSum(acc1[n] * ad1);
        if (c2 == 0 && ok) {
            g_as1[node] = make_float2(s0, s1);
            g_ad1[node] = make_float2(d0, d1);
        }
    }
}

// ---------------------------------------------------------------------------
// Gather layer1: warp per dst node, per-lane weight precompute, implicit
// self loop, fused normalize + bias + ELU -> feat2.
// ---------------------------------------------------------------------------
__global__ void g1_gather(const float* __restrict__ b1, int N) {
    int warp = threadIdx.x >> 5;
    int lane = threadIdx.x & 31;
    int node = blockIdx.x * 8 + warp;
    if (node >= N) return;

    float2 ad = g_ad1[node];
    int off = node * STRIDE;
    int deg = g_cur[node]; if (deg > STRIDE) deg = STRIDE;

    float2 acc = make_float2(0.f, 0.f);
    float den = 0.f;

    for (int j0 = 0; j0 < deg; j0 += 32) {
        int idx = j0 + lane;
        int myS = (idx < deg) ? g_srcs[off + idx] : 0;
        float w0l = 0.f, w1l = 0.f;
        if (idx < deg) {
            float2 as = g_as1[myS];
            float e0 = as.x + ad.x; e0 = (e0 > 0.f) ? e0 : 0.2f * e0;
            float e1 = as.y + ad.y; e1 = (e1 > 0.f) ? e1 : 0.2f * e1;
            w0l = __expf(e0);
            w1l = __expf(e1);
        }
        int cnt = deg - j0; if (cnt > 32) cnt = 32;
        if (cnt == 32) {
#pragma unroll 8
            for (int j = 0; j < 32; j++) {
                int   s  = __shfl_sync(0xffffffffu, myS, j);
                float w0 = __shfl_sync(0xffffffffu, w0l, j);
                float w1 = __shfl_sync(0xffffffffu, w1l, j);
                float w  = (lane < 16) ? w0 : w1;
                float2 hv = __half22float2(((const __half2*)(g_h1h + s * 64))[lane]);
                acc.x += w * hv.x; acc.y += w * hv.y;
                den += w;
            }
        } else {
            for (int j = 0; j < cnt; j++) {
                int   s  = __shfl_sync(0xffffffffu, myS, j);
                float w0 = __shfl_sync(0xffffffffu, w0l, j);
                float w1 = __shfl_sync(0xffffffffu, w1l, j);
                float w  = (lane < 16) ? w0 : w1;
                float2 hv = __half22float2(((const __half2*)(g_h1h + s * 64))[lane]);
                acc.x += w * hv.x; acc.y += w * hv.y;
                den += w;
            }
        }
    }

    // implicit self loop
    {
        float2 asn = g_as1[node];
        float e0 = asn.x + ad.x; e0 = (e0 > 0.f) ? e0 : 0.2f * e0;
        float e1 = asn.y + ad.y; e1 = (e1 > 0.f) ? e1 : 0.2f * e1;
        float ws = (lane < 16) ? __expf(e0) : __expf(e1);
        float2 hs = __half22float2(((const __half2*)(g_h1h + node * 64))[lane]);
        acc.x += ws * hs.x; acc.y += ws * hs.y;
        den += ws;
    }

    float inv = 1.f / den;
    float2 bv = ((const float2*)b1)[lane];
    float vx = acc.x * inv + bv.x;
    float vy = acc.y * inv + bv.y;
    vx = (vx > 0.f) ? vx : expm1f(vx);
    vy = (vy > 0.f) ? vy : expm1f(vy);
    ((float2*)(g_feat2 + node * 64))[lane] = make_float2(vx, vy);
}

// ---------------------------------------------------------------------------
// GEMM2: h2 = feat2 @ W2 (Nx64 @ 64x32) + alpha2 logits.
// 64 nodes/block; thread = (group gg=tid>>4 of 4 nodes, colpair c2/c2+16).
// smem 24KB, ~50 regs -> higher occupancy than round-7's 128-node tile.
// ---------------------------------------------------------------------------
__global__ void __launch_bounds__(256) k5_gemm2(
        const float* __restrict__ W2,
        const float* __restrict__ a_src,
        const float* __restrict__ a_dst, int N) {
    __shared__ float  Ws[64 * 32];
    __shared__ float4 xs[64 * 16];
    int tid = threadIdx.x;
    for (int i = tid; i < 64 * 32; i += 256) Ws[i] = W2[i];
    int node0 = blockIdx.x * 64;
    const float4* x4 = (const float4*)g_feat2;
    for (int i = tid; i < 1024; i += 256) {
        int gi = node0 * 16 + i;
        xs[i] = (gi < N * 16) ? x4[gi] : make_float4(0.f, 0.f, 0.f, 0.f);
    }
    __syncthreads();

    int c2 = tid & 15;          // cols c2, c2+16
    int gg = tid >> 4;          // 0..15 -> nodes gg*4..gg*4+3
    float acc0[4] = {0,0,0,0};
    float acc1[4] = {0,0,0,0};

#pragma unroll
    for (int kk = 0; kk < 64; kk += 8) {
        float w0[8], w1[8];
#pragma unroll
        for (int i = 0; i < 8; i++) {
            w0[i] = Ws[(kk + i) * 32 + c2];
            w1[i] = Ws[(kk + i) * 32 + c2 + 16];
        }
#pragma unroll
        for (int n = 0; n < 4; n++) {
            float4 xa = xs[(gg * 4 + n) * 16 + (kk >> 2)];
            float4 xb = xs[(gg * 4 + n) * 16 + (kk >> 2) + 1];
            acc0[n] += xa.x * w0[0] + xa.y * w0[1] + xa.z * w0[2] + xa.w * w0[3]
                     + xb.x * w0[4] + xb.y * w0[5] + xb.z * w0[6] + xb.w * w0[7];
            acc1[n] += xa.x * w1[0] + xa.y * w1[1] + xa.z * w1[2] + xa.w * w1[3]
                     + xb.x * w1[4] + xb.y * w1[5] + xb.z * w1[6] + xb.w * w1[7];
        }
    }

    float as0 = a_src[c2], as1 = a_src[c2 + 16];
    float ad0 = a_dst[c2], ad1 = a_dst[c2 + 16];

#pragma unroll
    for (int n = 0; n < 4; n++) {
        int node = node0 + gg * 4 + n;
        bool ok = node < N;
        if (ok) {
            g_h2h[node * 32 + c2]      = __float2half(acc0[n]);
            g_h2h[node * 32 + c2 + 16] = __float2half(acc1[n]);
        }
        float s = halfReduceSum(acc0[n] * as0 + acc1[n] * as1);
        float d = halfReduceSum(acc0[n] * ad0 + acc1[n] * ad1);
        if (c2 == 0 && ok) { g_as2[node] = s; g_ad2[node] = d; }
    }
}

// ---------------------------------------------------------------------------
// Gather layer2 + implicit self loop + fused epilogue. Re-zeroes g_cur.
// out[0:N] = scores, out[N:N+32N] = h row-major.
// ---------------------------------------------------------------------------
__global__ void g2_final(const float* __restrict__ b2,
                         const float* __restrict__ fcW,
                         const float* __restrict__ fcb,
                         float* __restrict__ out, int N) {
    int warp = threadIdx.x >> 5;
    int lane = threadIdx.x & 31;
    int node = blockIdx.x * 8 + warp;
    if (node >= N) return;

    float ad = g_ad2[node];
    int off = node * STRIDE;
    int deg = g_cur[node]; if (deg > STRIDE) deg = STRIDE;
    if (lane == 0) g_cur[node] = 0;      // restore launch invariant

    float acc = 0.f, den = 0.f;

    for (int j0 = 0; j0 < deg; j0 += 32) {
        int idx = j0 + lane;
        int myS = (idx < deg) ? g_srcs[off + idx] : 0;
        float wl = 0.f;
        if (idx < deg) {
            float e = g_as2[myS] + ad;
            e = (e > 0.f) ? e : 0.2f * e;
            wl = __expf(e);
        }
        int cnt = deg - j0; if (cnt > 32) cnt = 32;
        if (cnt == 32) {
#pragma unroll 8
            for (int j = 0; j < 32; j++) {
                int   s = __shfl_sync(0xffffffffu, myS, j);
                float w = __shfl_sync(0xffffffffu, wl, j);
                acc += w * __half2float(g_h2h[s * 32 + lane]);
                den += w;
            }
        } else {
            for (int j = 0; j < cnt; j++) {
                int   s = __shfl_sync(0xffffffffu, myS, j);
                float w = __shfl_sync(0xffffffffu, wl, j);
                acc += w * __half2float(g_h2h[s * 32 + lane]);
                den += w;
            }
        }
    }

    // implicit self loop
    {
        float es = g_as2[node] + ad;
        es = (es > 0.f) ? es : 0.2f * es;
        float ws = __expf(es);
        acc += ws * __half2float(g_h2h[node * 32 + lane]);
        den += ws;
    }

    float v = acc / den + b2[lane];
    v = (v > 0.f) ? v : expm1f(v);
    out[N + node * 32 + lane] = v;
    float sc = warpReduceSum(v * fcW[lane]);
    if (lane == 0) out[node] = sc + fcb[0];
}

extern "C" void kernel_launch(void* const* d_in, const int* in_sizes, int n_in,
                              void* d_out, int out_size) {
    const float* x      = (const float*)d_in[0];
    const int*   ei     = (const int*)d_in[1];
    const float* W1     = (const float*)d_in[2];
    const float* a_src1 = (const float*)d_in[3];
    const float* a_dst1 = (const float*)d_in[4];
    const float* b1     = (const float*)d_in[5];
    const float* W2     = (const float*)d_in[6];
    const float* a_src2 = (const float*)d_in[7];
    const float* a_dst2 = (const float*)d_in[8];
    const float* b2     = (const float*)d_in[9];
    const float* fcW    = (const float*)d_in[10];
    const float* fcb    = (const float*)d_in[11];
    float* out = (float*)d_out;

    int N = in_sizes[0] / 64;
    int E = in_sizes[1] / 2;

    int gemm1B = (N + 63) / 64;
    int fillB  = ((E >> 2) + 255) / 256;
    int gemm2B = (N + 63) / 64;
    int warpB  = (N + 7) / 8;

    k_fat<<<gemm1B + fillB, 256>>>(x, W1, a_src1, a_dst1, ei, N, E, gemm1B);
    g1_gather<<<warpB, 256>>>(b1, N);
    k5_gemm2<<<gemm2B, 256>>>(W2, a_src2, a_dst2, N);
    g2_final<<<warpB, 256>>>(b2, fcW, fcb, out, N);
}

// round 9
// speedup vs baseline: 1.4263x; 1.4263x over previous
#include <cuda_runtime.h>
#include <cuda_fp16.h>

// GATRoutingModel: 2-layer GAT + FC.  N=50000, E=1600000, F=64.
// Round 9: exact round-7 skeleton (k0_init + slot-0 self-loops + round-7
// gather bodies) + fp16 feat2 (halves gemm2 smem & traffic, occupancy 2->3
// blocks) + 8-edge/thread fill with bid%2 interleave.

#define NMAX   50000
#define EMAX   1600000
#define STRIDE 128

__device__ __half  g_h1h[NMAX * 64];
__device__ __half2 g_feat2h[NMAX * 32];   // elu(layer1) as half2 (cols 2l,2l+1)
__device__ __half  g_h2h[NMAX * 32];
__device__ float2  g_as1[NMAX];
__device__ float2  g_ad1[NMAX];
__device__ float   g_as2[NMAX];
__device__ float   g_ad2[NMAX];
__device__ int     g_cur[NMAX];
__device__ int     g_srcs[NMAX * STRIDE];

__device__ __forceinline__ float warpReduceSum(float v) {
#pragma unroll
    for (int o = 16; o > 0; o >>= 1) v += __shfl_xor_sync(0xffffffffu, v, o);
    return v;
}
__device__ __forceinline__ float halfReduceSum(float v) {
#pragma unroll
    for (int o = 8; o > 0; o >>= 1) v += __shfl_xor_sync(0xffffffffu, v, o);
    return v;
}

__global__ void k0_init(int N) {
    int i = blockIdx.x * blockDim.x + threadIdx.x;
    if (i < N) {
        g_cur[i] = 1;
        g_srcs[i * STRIDE] = i;     // self loop in slot 0
    }
}

// ---------------------------------------------------------------------------
// FAT kernel, interleaved roles: even bid (while gemm ids last) -> GEMM1
// block (64 nodes, 8n x 2c per thread); otherwise CSR slab fill
// (8 edges/thread via two int4 pairs).
// ---------------------------------------------------------------------------
__global__ void __launch_bounds__(256) k_fat(
        const float* __restrict__ x,
        const float* __restrict__ W1,
        const float* __restrict__ a_src,
        const float* __restrict__ a_dst,
        const int* __restrict__ ei,
        int N, int E, int gemmB) {
    int tid = threadIdx.x;
    int bid = blockIdx.x;
    int q = bid >> 1;
    bool isGemm = ((bid & 1) == 0) && (q < gemmB);

    if (!isGemm) {
        // -------- CSR fill: 8 edges/thread, slots from 1 (0 = self) --------
        int gcount = (bid + 1) >> 1; if (gcount > gemmB) gcount = gemmB;
        int fb = bid - gcount;
        int i = fb * 256 + tid;
        int n4 = E >> 2;                    // count of int4 groups
        const int4* src4 = (const int4*)ei;
        const int4* dst4 = (const int4*)(ei + E);
#pragma unroll
        for (int r = 0; r < 2; r++) {
            int g = i * 2 + r;
            if (g < n4) {
                int4 s = src4[g];
                int4 d = dst4[g];
                int p0 = atomicAdd(&g_cur[d.x], 1);
                int p1 = atomicAdd(&g_cur[d.y], 1);
                int p2 = atomicAdd(&g_cur[d.z], 1);
                int p3 = atomicAdd(&g_cur[d.w], 1);
                if (p0 < STRIDE) g_srcs[d.x * STRIDE + p0] = s.x;
                if (p1 < STRIDE) g_srcs[d.y * STRIDE + p1] = s.y;
                if (p2 < STRIDE) g_srcs[d.z * STRIDE + p2] = s.z;
                if (p3 < STRIDE) g_srcs[d.w * STRIDE + p3] = s.w;
            }
        }
        if (fb == 0 && tid == 0) {
            for (int t = n4 * 4; t < E; t++) {
                int d = ei[E + t];
                int p = atomicAdd(&g_cur[d], 1);
                if (p < STRIDE) g_srcs[d * STRIDE + p] = ei[t];
            }
        }
        return;
    }

    // -------- GEMM1: h1 = x @ W1 (Nx64 @ 64x64) + alpha1 logits --------
    __shared__ float  Ws[64 * 64];
    __shared__ float4 xs[64 * 16];
    for (int i = tid; i < 64 * 64; i += 256) Ws[i] = W1[i];
    int node0 = q * 64;
    const float4* x4 = (const float4*)x;
    for (int i = tid; i < 1024; i += 256) {
        int gi = node0 * 16 + i;
        xs[i] = (gi < N * 16) ? x4[gi] : make_float4(0.f, 0.f, 0.f, 0.f);
    }
    __syncthreads();

    int c2 = tid & 31;          // cols c2 (head0) and c2+32 (head1)
    int wp = tid >> 5;          // warp: nodes wp*8 .. wp*8+7
    float acc0[8] = {0,0,0,0,0,0,0,0};
    float acc1[8] = {0,0,0,0,0,0,0,0};

#pragma unroll
    for (int kk = 0; kk < 64; kk += 8) {
        float w0[8], w1[8];
#pragma unroll
        for (int i = 0; i < 8; i++) {
            w0[i] = Ws[(kk + i) * 64 + c2];
            w1[i] = Ws[(kk + i) * 64 + c2 + 32];
        }
#pragma unroll
        for (int n = 0; n < 8; n++) {
            float4 xa = xs[(wp * 8 + n) * 16 + (kk >> 2)];
            float4 xb = xs[(wp * 8 + n) * 16 + (kk >> 2) + 1];
            acc0[n] += xa.x * w0[0] + xa.y * w0[1] + xa.z * w0[2] + xa.w * w0[3]
                     + xb.x * w0[4] + xb.y * w0[5] + xb.z * w0[6] + xb.w * w0[7];
            acc1[n] += xa.x * w1[0] + xa.y * w1[1] + xa.z * w1[2] + xa.w * w1[3]
                     + xb.x * w1[4] + xb.y * w1[5] + xb.z * w1[6] + xb.w * w1[7];
        }
    }

    float as0 = a_src[c2], as1 = a_src[c2 + 32];
    float ad0 = a_dst[c2], ad1 = a_dst[c2 + 32];

#pragma unroll
    for (int n = 0; n < 8; n++) {
        int node = node0 + wp * 8 + n;
        bool ok = node < N;
        if (ok) {
            g_h1h[node * 64 + c2]      = __float2half(acc0[n]);
            g_h1h[node * 64 + c2 + 32] = __float2half(acc1[n]);
        }
        float s0 = warpReduceSum(acc0[n] * as0);
        float s1 = warpReduceSum(acc1[n] * as1);
        float d0 = warpReduceSum(acc0[n] * ad0);
        float d1 = warpReduceSum(acc1[n] * ad1);
        if (c2 == 0 && ok) {
            g_as1[node] = make_float2(s0, s1);
            g_ad1[node] = make_float2(d0, d1);
        }
    }
}

// ---------------------------------------------------------------------------
// Gather layer1 (round-7 body): warp per dst node, per-lane weight
// precompute, fused normalize + bias + ELU -> feat2 (half2).
// ---------------------------------------------------------------------------
__global__ void g1_gather(const float* __restrict__ b1, int N) {
    int warp = threadIdx.x >> 5;
    int lane = threadIdx.x & 31;
    int node = blockIdx.x * 8 + warp;
    if (node >= N) return;

    float2 ad = g_ad1[node];
    int off = node * STRIDE;
    int deg = g_cur[node]; if (deg > STRIDE) deg = STRIDE;

    float2 acc = make_float2(0.f, 0.f);
    float den = 0.f;

    for (int j0 = 0; j0 < deg; j0 += 32) {
        int idx = j0 + lane;
        int myS = (idx < deg) ? g_srcs[off + idx] : 0;
        float w0l = 0.f, w1l = 0.f;
        if (idx < deg) {
            float2 as = g_as1[myS];
            float e0 = as.x + ad.x; e0 = (e0 > 0.f) ? e0 : 0.2f * e0;
            float e1 = as.y + ad.y; e1 = (e1 > 0.f) ? e1 : 0.2f * e1;
            w0l = __expf(e0);
            w1l = __expf(e1);
        }
        int cnt = deg - j0; if (cnt > 32) cnt = 32;
        if (cnt == 32) {
#pragma unroll 8
            for (int j = 0; j < 32; j++) {
                int   s  = __shfl_sync(0xffffffffu, myS, j);
                float w0 = __shfl_sync(0xffffffffu, w0l, j);
                float w1 = __shfl_sync(0xffffffffu, w1l, j);
                float w  = (lane < 16) ? w0 : w1;
                float2 hv = __half22float2(((const __half2*)(g_h1h + s * 64))[lane]);
                acc.x += w * hv.x; acc.y += w * hv.y;
                den += w;
            }
        } else {
            for (int j = 0; j < cnt; j++) {
                int   s  = __shfl_sync(0xffffffffu, myS, j);
                float w0 = __shfl_sync(0xffffffffu, w0l, j);
                float w1 = __shfl_sync(0xffffffffu, w1l, j);
                float w  = (lane < 16) ? w0 : w1;
                float2 hv = __half22float2(((const __half2*)(g_h1h + s * 64))[lane]);
                acc.x += w * hv.x; acc.y += w * hv.y;
                den += w;
            }
        }
    }

    float inv = 1.f / den;
    float2 bv = ((const float2*)b1)[lane];
    float vx = acc.x * inv + bv.x;
    float vy = acc.y * inv + bv.y;
    vx = (vx > 0.f) ? vx : expm1f(vx);
    vy = (vy > 0.f) ? vy : expm1f(vy);
    g_feat2h[node * 32 + lane] = __floats2half2_rn(vx, vy);
}

// ---------------------------------------------------------------------------
// GEMM2: h2 = feat2 @ W2 (Nx64 @ 64x32) + alpha2 logits.
// Round-7 shape (128 nodes/block, 8n x 2c per thread) but x-tile in half:
// smem 24KB (was 41KB) -> 3 resident blocks; one LDS.128 per 8-k per node.
// ---------------------------------------------------------------------------
__global__ void __launch_bounds__(256) k5_gemm2(
        const float* __restrict__ W2,
        const float* __restrict__ a_src,
        const float* __restrict__ a_dst, int N) {
    __shared__ float Ws[64 * 32];
    __shared__ uint4 xs[128 * 8];       // 128 nodes x 64 halfs (8 halfs/uint4)
    int tid = threadIdx.x;
    for (int i = tid; i < 64 * 32; i += 256) Ws[i] = W2[i];
    int node0 = blockIdx.x * 128;
    const uint4* f4 = (const uint4*)g_feat2h;    // 8 halfs per uint4
    for (int i = tid; i < 1024; i += 256) {
        int gi = node0 * 8 + i;
        xs[i] = (gi < N * 8) ? f4[gi] : make_uint4(0u, 0u, 0u, 0u);
    }
    __syncthreads();

    int c2 = tid & 15;          // cols c2, c2+16
    int gg = tid >> 4;          // 0..15 -> nodes gg*8..gg*8+7
    float acc0[8] = {0,0,0,0,0,0,0,0};
    float acc1[8] = {0,0,0,0,0,0,0,0};

#pragma unroll
    for (int kk = 0; kk < 64; kk += 8) {
        float w0[8], w1[8];
#pragma unroll
        for (int i = 0; i < 8; i++) {
            w0[i] = Ws[(kk + i) * 32 + c2];
            w1[i] = Ws[(kk + i) * 32 + c2 + 16];
        }
#pragma unroll
        for (int n = 0; n < 8; n++) {
            uint4 xu = xs[(gg * 8 + n) * 8 + (kk >> 3)];
            float2 f0 = __half22float2(*(const __half2*)&xu.x);
            float2 f1 = __half22float2(*(const __half2*)&xu.y);
            float2 f2 = __half22float2(*(const __half2*)&xu.z);
            float2 f3 = __half22float2(*(const __half2*)&xu.w);
            acc0[n] += f0.x * w0[0] + f0.y * w0[1] + f1.x * w0[2] + f1.y * w0[3]
                     + f2.x * w0[4] + f2.y * w0[5] + f3.x * w0[6] + f3.y * w0[7];
            acc1[n] += f0.x * w1[0] + f0.y * w1[1] + f1.x * w1[2] + f1.y * w1[3]
                     + f2.x * w1[4] + f2.y * w1[5] + f3.x * w1[6] + f3.y * w1[7];
        }
    }

    float as0 = a_src[c2], as1 = a_src[c2 + 16];
    float ad0 = a_dst[c2], ad1 = a_dst[c2 + 16];

#pragma unroll
    for (int n = 0; n < 8; n++) {
        int node = node0 + gg * 8 + n;
        bool ok = node < N;
        if (ok) {
            g_h2h[node * 32 + c2]      = __float2half(acc0[n]);
            g_h2h[node * 32 + c2 + 16] = __float2half(acc1[n]);
        }
        float s = halfReduceSum(acc0[n] * as0 + acc1[n] * as1);
        float d = halfReduceSum(acc0[n] * ad0 + acc1[n] * ad1);
        if (c2 == 0 && ok) { g_as2[node] = s; g_ad2[node] = d; }
    }
}

// ---------------------------------------------------------------------------
// Gather layer2 + fused epilogue (round-7 body).
// out[0:N] = scores, out[N:N+32N] = h row-major.
// ---------------------------------------------------------------------------
__global__ void g2_final(const float* __restrict__ b2,
                         const float* __restrict__ fcW,
                         const float* __restrict__ fcb,
                         float* __restrict__ out, int N) {
    int warp = threadIdx.x >> 5;
    int lane = threadIdx.x & 31;
    int node = blockIdx.x * 8 + warp;
    if (node >= N) return;

    float ad = g_ad2[node];
    int off = node * STRIDE;
    int deg = g_cur[node]; if (deg > STRIDE) deg = STRIDE;

    float acc = 0.f, den = 0.f;

    for (int j0 = 0; j0 < deg; j0 += 32) {
        int idx = j0 + lane;
        int myS = (idx < deg) ? g_srcs[off + idx] : 0;
        float wl = 0.f;
        if (idx < deg) {
            float e = g_as2[myS] + ad;
            e = (e > 0.f) ? e : 0.2f * e;
            wl = __expf(e);
        }
        int cnt = deg - j0; if (cnt > 32) cnt = 32;
        if (cnt == 32) {
#pragma unroll 8
            for (int j = 0; j < 32; j++) {
                int   s = __shfl_sync(0xffffffffu, myS, j);
                float w = __shfl_sync(0xffffffffu, wl, j);
                acc += w * __half2float(g_h2h[s * 32 + lane]);
                den += w;
            }
        } else {
            for (int j = 0; j < cnt; j++) {
                int   s = __shfl_sync(0xffffffffu, myS, j);
                float w = __shfl_sync(0xffffffffu, wl, j);
                acc += w * __half2float(g_h2h[s * 32 + lane]);
                den += w;
            }
        }
    }

    float v = acc / den + b2[lane];
    v = (v > 0.f) ? v : expm1f(v);
    out[N + node * 32 + lane] = v;
    float sc = warpReduceSum(v * fcW[lane]);
    if (lane == 0) out[node] = sc + fcb[0];
}

extern "C" void kernel_launch(void* const* d_in, const int* in_sizes, int n_in,
                              void* d_out, int out_size) {
    const float* x      = (const float*)d_in[0];
    const int*   ei     = (const int*)d_in[1];
    const float* W1     = (const float*)d_in[2];
    const float* a_src1 = (const float*)d_in[3];
    const float* a_dst1 = (const float*)d_in[4];
    const float* b1     = (const float*)d_in[5];
    const float* W2     = (const float*)d_in[6];
    const float* a_src2 = (const float*)d_in[7];
    const float* a_dst2 = (const float*)d_in[8];
    const float* b2     = (const float*)d_in[9];
    const float* fcW    = (const float*)d_in[10];
    const float* fcb    = (const float*)d_in[11];
    float* out = (float*)d_out;

    int N = in_sizes[0] / 64;
    int E = in_sizes[1] / 2;

    int nB     = (N + 255) / 256;
    int gemm1B = (N + 63) / 64;
    int fillB  = ((E >> 3) + 255) / 256;     // 8 edges/thread
    int gemm2B = (N + 127) / 128;
    int warpB  = (N + 7) / 8;

    k0_init<<<nB, 256>>>(N);
    k_fat<<<gemm1B + fillB, 256>>>(x, W1, a_src1, a_dst1, ei, N, E, gemm1B);
    g1_gather<<<warpB, 256>>>(b1, N);
    k5_gemm2<<<gemm2B, 256>>>(W2, a_src2, a_dst2, N);
    g2_final<<<warpB, 256>>>(b2, fcW, fcb, out, N);
}